// round 1
// baseline (speedup 1.0000x reference)
#include <cuda_runtime.h>
#include <math.h>

#define TT   4096      // tokens
#define EE   8         // experts
#define HH   1024      // hidden
#define DFFC 2048      // d_ff
#define KSEL 2         // top-k
#define PP   (TT*KSEL) // total routed pairs = 8192

// ---------------- scratch (static device globals: allocation-free) ----------
__device__ int   g_cnt[EE];
__device__ int   g_base[EE];
__device__ int   g_tok[EE][TT];
__device__ float g_wt [EE][TT];
__device__ float g_inter[PP][DFFC];   // 64 MiB intermediate silu(g)*u

// ---------------- kernel 1: reset counters + zero output --------------------
__global__ void k_zero(float* out) {
    int i = blockIdx.x * blockDim.x + threadIdx.x;
    if (i < EE) g_cnt[i] = 0;
    for (size_t j = i; j < (size_t)TT * HH; j += (size_t)gridDim.x * blockDim.x)
        out[j] = 0.f;
}

// ---------------- kernel 2: router (1 warp per token) -----------------------
__global__ void k_router(const float* __restrict__ x,
                         const float* __restrict__ cent,
                         const float* __restrict__ bias) {
    int warp = threadIdx.x >> 5;
    int lane = threadIdx.x & 31;
    int t = blockIdx.x * 8 + warp;
    if (t >= TT) return;
    const float* xr = x + (size_t)t * HH;

    float acc[EE];
#pragma unroll
    for (int e = 0; e < EE; e++) acc[e] = 0.f;

    for (int h = lane; h < HH; h += 32) {
        float xv = xr[h];
#pragma unroll
        for (int e = 0; e < EE; e++) acc[e] += xv * cent[e * HH + h];
    }
#pragma unroll
    for (int e = 0; e < EE; e++) {
#pragma unroll
        for (int o = 16; o > 0; o >>= 1)
            acc[e] += __shfl_down_sync(0xffffffffu, acc[e], o);
    }

    if (lane == 0) {
        float s[EE];
#pragma unroll
        for (int e = 0; e < EE; e++)
            s[e] = 1.f / (1.f + expf(-acc[e])) + bias[e];

        // top-2 (earliest index wins ties, matching lax.top_k)
        float v0 = -1e30f; int i0 = 0;
#pragma unroll
        for (int e = 0; e < EE; e++) if (s[e] > v0) { v0 = s[e]; i0 = e; }
        float v1 = -1e30f; int i1 = 0;
#pragma unroll
        for (int e = 0; e < EE; e++) if (e != i0 && s[e] > v1) { v1 = s[e]; i1 = e; }

        float e1 = expf(v1 - v0);
        float w0 = 1.f / (1.f + e1);
        float w1 = e1 * w0;

        int s0 = atomicAdd(&g_cnt[i0], 1);
        g_tok[i0][s0] = t;  g_wt[i0][s0] = w0;
        int s1 = atomicAdd(&g_cnt[i1], 1);
        g_tok[i1][s1] = t;  g_wt[i1][s1] = w1;
    }
}

// ---------------- kernel 3: prefix sum + counts output ----------------------
__global__ void k_prefix(float* out, int write_counts) {
    if (threadIdx.x == 0) {
        int b = 0;
        for (int e = 0; e < EE; e++) { g_base[e] = b; b += g_cnt[e]; }
    }
    __syncthreads();
    if (write_counts && threadIdx.x < EE)
        out[(size_t)TT * HH + threadIdx.x] = (float)g_cnt[threadIdx.x];
}

// ---------------- kernel 4: grouped gate/up GEMM + SwiGLU -------------------
// Tile: 64 rows (tokens) x 64 cols (dff), K = HH, TK = 16. 256 thr, 4x4 micro.
__global__ __launch_bounds__(256) void k_gateup(const float* __restrict__ x,
                                                const float* __restrict__ gw,
                                                const float* __restrict__ uw) {
    int e   = blockIdx.z;
    int cnt = g_cnt[e];
    int r0  = blockIdx.y * 64;
    if (r0 >= cnt) return;
    int n0  = blockIdx.x * 64;

    __shared__ __align__(16) float As[16][68];
    __shared__ __align__(16) float Bg[16][68];
    __shared__ __align__(16) float Bu[16][68];
    __shared__ int toks[64];

    int tid = threadIdx.x;
    if (tid < 64) toks[tid] = (r0 + tid < cnt) ? g_tok[e][r0 + tid] : -1;
    __syncthreads();

    int lr = tid >> 2;          // load row 0..63
    int lq = (tid & 3) * 4;     // k sub-offset 0/4/8/12
    int ty = tid >> 4;          // 0..15
    int tx = tid & 15;          // 0..15

    int at = toks[lr];
    const float* arow  = x + (size_t)(at < 0 ? 0 : at) * HH;
    const float* gbase = gw + ((size_t)e * DFFC + n0 + lr) * HH;
    const float* ubase = uw + ((size_t)e * DFFC + n0 + lr) * HH;

    float cg[4][4], cu[4][4];
#pragma unroll
    for (int i = 0; i < 4; i++)
#pragma unroll
        for (int j = 0; j < 4; j++) { cg[i][j] = 0.f; cu[i][j] = 0.f; }

    for (int kk = 0; kk < HH; kk += 16) {
        float4 av = make_float4(0.f, 0.f, 0.f, 0.f);
        if (at >= 0) av = *(const float4*)(arow + kk + lq);
        float4 gv = *(const float4*)(gbase + kk + lq);
        float4 uv = *(const float4*)(ubase + kk + lq);

        As[lq + 0][lr] = av.x; As[lq + 1][lr] = av.y;
        As[lq + 2][lr] = av.z; As[lq + 3][lr] = av.w;
        Bg[lq + 0][lr] = gv.x; Bg[lq + 1][lr] = gv.y;
        Bg[lq + 2][lr] = gv.z; Bg[lq + 3][lr] = gv.w;
        Bu[lq + 0][lr] = uv.x; Bu[lq + 1][lr] = uv.y;
        Bu[lq + 2][lr] = uv.z; Bu[lq + 3][lr] = uv.w;
        __syncthreads();

#pragma unroll
        for (int k = 0; k < 16; k++) {
            float4 a  = *(const float4*)(&As[k][ty * 4]);
            float4 bg = *(const float4*)(&Bg[k][tx * 4]);
            float4 bu = *(const float4*)(&Bu[k][tx * 4]);
            float aa[4] = {a.x, a.y, a.z, a.w};
            float gg[4] = {bg.x, bg.y, bg.z, bg.w};
            float uu[4] = {bu.x, bu.y, bu.z, bu.w};
#pragma unroll
            for (int i = 0; i < 4; i++)
#pragma unroll
                for (int j = 0; j < 4; j++) {
                    cg[i][j] += aa[i] * gg[j];
                    cu[i][j] += aa[i] * uu[j];
                }
        }
        __syncthreads();
    }

    int pbase = g_base[e] + r0;
#pragma unroll
    for (int i = 0; i < 4; i++) {
        int row = ty * 4 + i;
        if (r0 + row < cnt) {
            float4 h;
            float g0 = cg[i][0], g1 = cg[i][1], g2 = cg[i][2], g3 = cg[i][3];
            h.x = (g0 / (1.f + expf(-g0))) * cu[i][0];
            h.y = (g1 / (1.f + expf(-g1))) * cu[i][1];
            h.z = (g2 / (1.f + expf(-g2))) * cu[i][2];
            h.w = (g3 / (1.f + expf(-g3))) * cu[i][3];
            *(float4*)(&g_inter[pbase + row][n0 + tx * 4]) = h;
        }
    }
}

// ---------------- kernel 5: grouped down GEMM + weighted scatter ------------
// Tile: 64 rows (pairs) x 64 cols (H), K = DFF, TK = 16.
__global__ __launch_bounds__(256) void k_down(const float* __restrict__ dw,
                                              float* __restrict__ out) {
    int e   = blockIdx.z;
    int cnt = g_cnt[e];
    int r0  = blockIdx.y * 64;
    if (r0 >= cnt) return;
    int n0  = blockIdx.x * 64;

    __shared__ __align__(16) float As[16][68];
    __shared__ __align__(16) float Bs[16][68];
    __shared__ int   toks[64];
    __shared__ float ws[64];

    int tid = threadIdx.x;
    if (tid < 64) {
        bool ok = (r0 + tid < cnt);
        toks[tid] = ok ? g_tok[e][r0 + tid] : 0;
        ws[tid]   = ok ? g_wt [e][r0 + tid] : 0.f;
    }
    __syncthreads();

    int lr = tid >> 2;
    int lq = (tid & 3) * 4;
    int ty = tid >> 4;
    int tx = tid & 15;

    bool aok = (r0 + lr) < cnt;
    int  pr  = aok ? (g_base[e] + r0 + lr) : 0;
    const float* arow = &g_inter[pr][0];
    const float* brow = dw + ((size_t)e * HH + n0 + lr) * DFFC;

    float c[4][4];
#pragma unroll
    for (int i = 0; i < 4; i++)
#pragma unroll
        for (int j = 0; j < 4; j++) c[i][j] = 0.f;

    for (int kk = 0; kk < DFFC; kk += 16) {
        float4 av = make_float4(0.f, 0.f, 0.f, 0.f);
        if (aok) av = *(const float4*)(arow + kk + lq);
        float4 bv = *(const float4*)(brow + kk + lq);

        As[lq + 0][lr] = av.x; As[lq + 1][lr] = av.y;
        As[lq + 2][lr] = av.z; As[lq + 3][lr] = av.w;
        Bs[lq + 0][lr] = bv.x; Bs[lq + 1][lr] = bv.y;
        Bs[lq + 2][lr] = bv.z; Bs[lq + 3][lr] = bv.w;
        __syncthreads();

#pragma unroll
        for (int k = 0; k < 16; k++) {
            float4 a = *(const float4*)(&As[k][ty * 4]);
            float4 b = *(const float4*)(&Bs[k][tx * 4]);
            float aa[4] = {a.x, a.y, a.z, a.w};
            float bb[4] = {b.x, b.y, b.z, b.w};
#pragma unroll
            for (int i = 0; i < 4; i++)
#pragma unroll
                for (int j = 0; j < 4; j++) c[i][j] += aa[i] * bb[j];
        }
        __syncthreads();
    }

#pragma unroll
    for (int i = 0; i < 4; i++) {
        int row = ty * 4 + i;
        if (r0 + row < cnt) {
            int   t = toks[row];
            float w = ws[row];
            float* dst = out + (size_t)t * HH + n0 + tx * 4;
            atomicAdd(dst + 0, w * c[i][0]);
            atomicAdd(dst + 1, w * c[i][1]);
            atomicAdd(dst + 2, w * c[i][2]);
            atomicAdd(dst + 3, w * c[i][3]);
        }
    }
}

// ---------------- launch -----------------------------------------------------
extern "C" void kernel_launch(void* const* d_in, const int* in_sizes, int n_in,
                              void* d_out, int out_size) {
    const float* x    = (const float*)d_in[0];   // [4,1024,1024]
    const float* cent = (const float*)d_in[1];   // [8,1024]
    const float* gw   = (const float*)d_in[2];   // [8,2048,1024]
    const float* uw   = (const float*)d_in[3];   // [8,2048,1024]
    const float* dw   = (const float*)d_in[4];   // [8,1024,2048]
    const float* bias = (const float*)d_in[5];   // [8]
    float* out = (float*)d_out;

    int write_counts = (out_size >= TT * HH + EE) ? 1 : 0;

    k_zero<<<2048, 256>>>(out);
    k_router<<<TT / 8, 256>>>(x, cent, bias);
    k_prefix<<<1, 32>>>(out, write_counts);
    k_gateup<<<dim3(DFFC / 64, TT / 64, EE), 256>>>(x, gw, uw);
    k_down  <<<dim3(HH   / 64, TT / 64, EE), 256>>>(dw, out);
}

// round 2
// speedup vs baseline: 1.8318x; 1.8318x over previous
#include <cuda_runtime.h>
#include <cuda_bf16.h>
#include <math.h>

#define TT   4096
#define EE   8
#define HH   1024
#define DFFC 2048
#define PP   (TT*2)

// ---------------- device scratch ----------------
__device__ int   g_cnt[EE];
__device__ int   g_base[EE];
__device__ int   g_tok[EE][TT];
__device__ float g_wt [EE][TT];

__device__ __nv_bfloat16 g_xh[TT*HH],        g_xl[TT*HH];
__device__ __nv_bfloat16 g_gwh[EE*DFFC*HH],  g_gwl[EE*DFFC*HH];
__device__ __nv_bfloat16 g_uwh[EE*DFFC*HH],  g_uwl[EE*DFFC*HH];
__device__ __nv_bfloat16 g_dwh[EE*HH*DFFC],  g_dwl[EE*HH*DFFC];
__device__ __nv_bfloat16 g_ih[(size_t)PP*DFFC], g_il[(size_t)PP*DFFC];

// ---------------- mma / ldmatrix helpers ----------------
__device__ __forceinline__ void ldsm4(unsigned &r0, unsigned &r1, unsigned &r2, unsigned &r3,
                                      unsigned addr) {
    asm volatile("ldmatrix.sync.aligned.m8n8.x4.shared.b16 {%0,%1,%2,%3}, [%4];"
                 : "=r"(r0), "=r"(r1), "=r"(r2), "=r"(r3) : "r"(addr));
}
__device__ __forceinline__ void mma16816(float c[4], const unsigned a[4],
                                         unsigned b0, unsigned b1) {
    asm volatile("mma.sync.aligned.m16n8k16.row.col.f32.bf16.bf16.f32 "
                 "{%0,%1,%2,%3}, {%4,%5,%6,%7}, {%8,%9}, {%0,%1,%2,%3};"
                 : "+f"(c[0]), "+f"(c[1]), "+f"(c[2]), "+f"(c[3])
                 : "r"(a[0]), "r"(a[1]), "r"(a[2]), "r"(a[3]), "r"(b0), "r"(b1));
}
// A fragment: 16x16 tile at (m0, k=ks*16) from 80B-stride smem tile
__device__ __forceinline__ void ldfragA(unsigned f[4], unsigned base, int m0, int ks, int lane) {
    int sub = lane >> 3;
    int r   = m0 + (lane & 7) + ((sub & 1) << 3);
    int kg  = (ks << 1) + (sub >> 1);
    ldsm4(f[0], f[1], f[2], f[3], base + r * 80 + (kg << 4));
}
// B fragments for two adjacent n8 tiles (n0..n0+15) at k=ks*16
__device__ __forceinline__ void ldfragB(unsigned f[4], unsigned base, int n0, int ks, int lane) {
    int sub = lane >> 3;
    int r   = n0 + (lane & 7) + ((sub >> 1) << 3);
    int kg  = (ks << 1) + (sub & 1);
    ldsm4(f[0], f[1], f[2], f[3], base + r * 80 + (kg << 4));
}
__device__ __forceinline__ __nv_bfloat16 bfhi(float a) { return __float2bfloat16(a); }
__device__ __forceinline__ __nv_bfloat16 bflo(float a, __nv_bfloat16 h) {
    return __float2bfloat16(a - __bfloat162float(h));
}

// ---------------- kernel: zero out + counters ----------------
__global__ void k_zero(float* out) {
    int i = blockIdx.x * blockDim.x + threadIdx.x;
    if (i < EE) g_cnt[i] = 0;
    for (size_t j = i; j < (size_t)TT * HH; j += (size_t)gridDim.x * blockDim.x)
        out[j] = 0.f;
}

// ---------------- kernel: split fp32 -> bf16 hi/lo (weights + x) ------------
#define NG4 (EE*DFFC*HH/4)
#define NX4 (TT*HH/4)
__global__ void k_split(const float4* __restrict__ gw, const float4* __restrict__ uw,
                        const float4* __restrict__ dw, const float4* __restrict__ x) {
    int i = blockIdx.x * blockDim.x + threadIdx.x;
    const float4* src; __nv_bfloat16* hi; __nv_bfloat16* lo; int idx;
    if      (i < NG4)          { src = gw; hi = g_gwh; lo = g_gwl; idx = i; }
    else if (i < 2*NG4)        { src = uw; hi = g_uwh; lo = g_uwl; idx = i - NG4; }
    else if (i < 3*NG4)        { src = dw; hi = g_dwh; lo = g_dwl; idx = i - 2*NG4; }
    else if (i < 3*NG4 + NX4)  { src = x;  hi = g_xh;  lo = g_xl;  idx = i - 3*NG4; }
    else return;
    float4 v = src[idx];
    __nv_bfloat162 h0, h1, l0, l1;
    h0.x = bfhi(v.x); l0.x = bflo(v.x, h0.x);
    h0.y = bfhi(v.y); l0.y = bflo(v.y, h0.y);
    h1.x = bfhi(v.z); l1.x = bflo(v.z, h1.x);
    h1.y = bfhi(v.w); l1.y = bflo(v.w, h1.y);
    ((__nv_bfloat162*)hi)[2*idx] = h0; ((__nv_bfloat162*)hi)[2*idx+1] = h1;
    ((__nv_bfloat162*)lo)[2*idx] = l0; ((__nv_bfloat162*)lo)[2*idx+1] = l1;
}

// ---------------- kernel: router ----------------
__global__ void k_router(const float* __restrict__ x, const float* __restrict__ cent,
                         const float* __restrict__ bias) {
    int warp = threadIdx.x >> 5, lane = threadIdx.x & 31;
    int t = blockIdx.x * 8 + warp;
    if (t >= TT) return;
    const float* xr = x + (size_t)t * HH;
    float acc[EE];
#pragma unroll
    for (int e = 0; e < EE; e++) acc[e] = 0.f;
    for (int h = lane; h < HH; h += 32) {
        float xv = xr[h];
#pragma unroll
        for (int e = 0; e < EE; e++) acc[e] += xv * cent[e * HH + h];
    }
#pragma unroll
    for (int e = 0; e < EE; e++)
#pragma unroll
        for (int o = 16; o > 0; o >>= 1)
            acc[e] += __shfl_down_sync(0xffffffffu, acc[e], o);
    if (lane == 0) {
        float s[EE];
#pragma unroll
        for (int e = 0; e < EE; e++)
            s[e] = 1.f / (1.f + expf(-acc[e])) + bias[e];
        float v0 = -1e30f; int i0 = 0;
#pragma unroll
        for (int e = 0; e < EE; e++) if (s[e] > v0) { v0 = s[e]; i0 = e; }
        float v1 = -1e30f; int i1 = 0;
#pragma unroll
        for (int e = 0; e < EE; e++) if (e != i0 && s[e] > v1) { v1 = s[e]; i1 = e; }
        float e1 = expf(v1 - v0);
        float w0 = 1.f / (1.f + e1), w1 = e1 * w0;
        int s0 = atomicAdd(&g_cnt[i0], 1);
        g_tok[i0][s0] = t; g_wt[i0][s0] = w0;
        int s1 = atomicAdd(&g_cnt[i1], 1);
        g_tok[i1][s1] = t; g_wt[i1][s1] = w1;
    }
}

__global__ void k_prefix(float* out, int write_counts) {
    if (threadIdx.x == 0) {
        int b = 0;
        for (int e = 0; e < EE; e++) { g_base[e] = b; b += g_cnt[e]; }
    }
    __syncthreads();
    if (write_counts && threadIdx.x < EE)
        out[(size_t)TT * HH + threadIdx.x] = (float)g_cnt[threadIdx.x];
}

// ---------------- kernel: gate/up grouped GEMM + SwiGLU (tensor core) -------
// Block: 64 tokens x 64 dff, BK=32, 256 thr (8 warps, warp tile 16x32, both g,u)
__global__ __launch_bounds__(256) void k_gateup() {
    int e   = blockIdx.z;
    int cnt = g_cnt[e];
    int r0  = blockIdx.y * 64;
    if (r0 >= cnt) return;
    int n0b = blockIdx.x * 64;

    __shared__ __align__(16) unsigned char sAh[64*80], sAl[64*80];
    __shared__ __align__(16) unsigned char sGh[64*80], sGl[64*80];
    __shared__ __align__(16) unsigned char sUh[64*80], sUl[64*80];
    __shared__ int toks[64];

    int tid = threadIdx.x, lane = tid & 31, warp = tid >> 5;
    if (tid < 64) toks[tid] = (r0 + tid < cnt) ? g_tok[e][r0 + tid] : -1;
    __syncthreads();

    unsigned bAh = (unsigned)__cvta_generic_to_shared(sAh);
    unsigned bAl = (unsigned)__cvta_generic_to_shared(sAl);
    unsigned bGh = (unsigned)__cvta_generic_to_shared(sGh);
    unsigned bGl = (unsigned)__cvta_generic_to_shared(sGl);
    unsigned bUh = (unsigned)__cvta_generic_to_shared(sUh);
    unsigned bUl = (unsigned)__cvta_generic_to_shared(sUl);

    int lr = tid >> 2, lkg = tid & 3;        // one 16B granule per thread per tile
    int at = toks[lr]; int ats = at < 0 ? 0 : at;
    const __nv_bfloat16* pxh = g_xh + (size_t)ats * HH + lkg * 8;
    const __nv_bfloat16* pxl = g_xl + (size_t)ats * HH + lkg * 8;
    size_t woff = ((size_t)e * DFFC + n0b + lr) * HH + lkg * 8;
    const __nv_bfloat16* pgh = g_gwh + woff; const __nv_bfloat16* pgl = g_gwl + woff;
    const __nv_bfloat16* puh = g_uwh + woff; const __nv_bfloat16* pul = g_uwl + woff;
    unsigned sdst = lr * 80 + (lkg << 4);

    int wm = warp >> 1, wn = warp & 1;
    int m0 = wm * 16, nw0 = wn * 32;

    float cg[4][4], cu[4][4];
#pragma unroll
    for (int i = 0; i < 4; i++)
#pragma unroll
        for (int j = 0; j < 4; j++) { cg[i][j] = 0.f; cu[i][j] = 0.f; }

    for (int kk = 0; kk < HH; kk += 32) {
        uint4 vah = *(const uint4*)(pxh + kk), val_ = *(const uint4*)(pxl + kk);
        uint4 vgh = *(const uint4*)(pgh + kk), vgl = *(const uint4*)(pgl + kk);
        uint4 vuh = *(const uint4*)(puh + kk), vul = *(const uint4*)(pul + kk);
        *(uint4*)(sAh + sdst) = vah; *(uint4*)(sAl + sdst) = val_;
        *(uint4*)(sGh + sdst) = vgh; *(uint4*)(sGl + sdst) = vgl;
        *(uint4*)(sUh + sdst) = vuh; *(uint4*)(sUl + sdst) = vul;
        __syncthreads();

#pragma unroll
        for (int ks = 0; ks < 2; ks++) {
            unsigned ah[4], al[4], fh[4], fl[4];
            ldfragA(ah, bAh, m0, ks, lane);
            ldfragA(al, bAl, m0, ks, lane);
            // gate, n tiles 0-1
            ldfragB(fh, bGh, nw0, ks, lane); ldfragB(fl, bGl, nw0, ks, lane);
            mma16816(cg[0], ah, fh[0], fh[1]); mma16816(cg[0], ah, fl[0], fl[1]);
            mma16816(cg[0], al, fh[0], fh[1]);
            mma16816(cg[1], ah, fh[2], fh[3]); mma16816(cg[1], ah, fl[2], fl[3]);
            mma16816(cg[1], al, fh[2], fh[3]);
            // gate, n tiles 2-3
            ldfragB(fh, bGh, nw0 + 16, ks, lane); ldfragB(fl, bGl, nw0 + 16, ks, lane);
            mma16816(cg[2], ah, fh[0], fh[1]); mma16816(cg[2], ah, fl[0], fl[1]);
            mma16816(cg[2], al, fh[0], fh[1]);
            mma16816(cg[3], ah, fh[2], fh[3]); mma16816(cg[3], ah, fl[2], fl[3]);
            mma16816(cg[3], al, fh[2], fh[3]);
            // up, n tiles 0-1
            ldfragB(fh, bUh, nw0, ks, lane); ldfragB(fl, bUl, nw0, ks, lane);
            mma16816(cu[0], ah, fh[0], fh[1]); mma16816(cu[0], ah, fl[0], fl[1]);
            mma16816(cu[0], al, fh[0], fh[1]);
            mma16816(cu[1], ah, fh[2], fh[3]); mma16816(cu[1], ah, fl[2], fl[3]);
            mma16816(cu[1], al, fh[2], fh[3]);
            // up, n tiles 2-3
            ldfragB(fh, bUh, nw0 + 16, ks, lane); ldfragB(fl, bUl, nw0 + 16, ks, lane);
            mma16816(cu[2], ah, fh[0], fh[1]); mma16816(cu[2], ah, fl[0], fl[1]);
            mma16816(cu[2], al, fh[0], fh[1]);
            mma16816(cu[3], ah, fh[2], fh[3]); mma16816(cu[3], ah, fl[2], fl[3]);
            mma16816(cu[3], al, fh[2], fh[3]);
        }
        __syncthreads();
    }

    // epilogue: silu(g)*u, split to bf16 hi/lo, store to intermediate
    int rl0 = m0 + (lane >> 2);
    int cbase = n0b + nw0 + (lane & 3) * 2;
    int pb = g_base[e] + r0;
#pragma unroll
    for (int half = 0; half < 2; half++) {
        int rl = rl0 + half * 8;
        if (r0 + rl < cnt) {
            size_t p = (size_t)(pb + rl);
#pragma unroll
            for (int nt = 0; nt < 4; nt++) {
                int col = cbase + nt * 8;
                float gg0 = cg[nt][half*2+0], gg1 = cg[nt][half*2+1];
                float uu0 = cu[nt][half*2+0], uu1 = cu[nt][half*2+1];
                float h0 = (gg0 / (1.f + expf(-gg0))) * uu0;
                float h1 = (gg1 / (1.f + expf(-gg1))) * uu1;
                __nv_bfloat162 vh, vl;
                vh.x = bfhi(h0); vl.x = bflo(h0, vh.x);
                vh.y = bfhi(h1); vl.y = bflo(h1, vh.y);
                *(__nv_bfloat162*)(g_ih + p * DFFC + col) = vh;
                *(__nv_bfloat162*)(g_il + p * DFFC + col) = vl;
            }
        }
    }
}

// ---------------- kernel: down grouped GEMM + weighted scatter (tensor) -----
__global__ __launch_bounds__(256) void k_down(float* __restrict__ out) {
    int e   = blockIdx.z;
    int cnt = g_cnt[e];
    int r0  = blockIdx.y * 64;
    if (r0 >= cnt) return;
    int n0b = blockIdx.x * 64;

    __shared__ __align__(16) unsigned char sAh[64*80], sAl[64*80];
    __shared__ __align__(16) unsigned char sBh[64*80], sBl[64*80];
    __shared__ int   toks[64];
    __shared__ float ws[64];

    int tid = threadIdx.x, lane = tid & 31, warp = tid >> 5;
    if (tid < 64) {
        bool ok = (r0 + tid < cnt);
        toks[tid] = ok ? g_tok[e][r0 + tid] : 0;
        ws[tid]   = ok ? g_wt [e][r0 + tid] : 0.f;
    }
    __syncthreads();

    unsigned bAh = (unsigned)__cvta_generic_to_shared(sAh);
    unsigned bAl = (unsigned)__cvta_generic_to_shared(sAl);
    unsigned bBh = (unsigned)__cvta_generic_to_shared(sBh);
    unsigned bBl = (unsigned)__cvta_generic_to_shared(sBl);

    int lr = tid >> 2, lkg = tid & 3;
    int prow = (r0 + lr < cnt) ? (g_base[e] + r0 + lr) : 0;
    const __nv_bfloat16* pih = g_ih + (size_t)prow * DFFC + lkg * 8;
    const __nv_bfloat16* pil = g_il + (size_t)prow * DFFC + lkg * 8;
    size_t woff = ((size_t)e * HH + n0b + lr) * DFFC + lkg * 8;
    const __nv_bfloat16* pdh = g_dwh + woff; const __nv_bfloat16* pdl = g_dwl + woff;
    unsigned sdst = lr * 80 + (lkg << 4);

    int wm = warp >> 1, wn = warp & 1;
    int m0 = wm * 16, nw0 = wn * 32;

    float c[4][4];
#pragma unroll
    for (int i = 0; i < 4; i++)
#pragma unroll
        for (int j = 0; j < 4; j++) c[i][j] = 0.f;

    for (int kk = 0; kk < DFFC; kk += 32) {
        uint4 vah = *(const uint4*)(pih + kk), val_ = *(const uint4*)(pil + kk);
        uint4 vbh = *(const uint4*)(pdh + kk), vbl = *(const uint4*)(pdl + kk);
        *(uint4*)(sAh + sdst) = vah; *(uint4*)(sAl + sdst) = val_;
        *(uint4*)(sBh + sdst) = vbh; *(uint4*)(sBl + sdst) = vbl;
        __syncthreads();

#pragma unroll
        for (int ks = 0; ks < 2; ks++) {
            unsigned ah[4], al[4], fh[4], fl[4];
            ldfragA(ah, bAh, m0, ks, lane);
            ldfragA(al, bAl, m0, ks, lane);
            ldfragB(fh, bBh, nw0, ks, lane); ldfragB(fl, bBl, nw0, ks, lane);
            mma16816(c[0], ah, fh[0], fh[1]); mma16816(c[0], ah, fl[0], fl[1]);
            mma16816(c[0], al, fh[0], fh[1]);
            mma16816(c[1], ah, fh[2], fh[3]); mma16816(c[1], ah, fl[2], fl[3]);
            mma16816(c[1], al, fh[2], fh[3]);
            ldfragB(fh, bBh, nw0 + 16, ks, lane); ldfragB(fl, bBl, nw0 + 16, ks, lane);
            mma16816(c[2], ah, fh[0], fh[1]); mma16816(c[2], ah, fl[0], fl[1]);
            mma16816(c[2], al, fh[0], fh[1]);
            mma16816(c[3], ah, fh[2], fh[3]); mma16816(c[3], ah, fl[2], fl[3]);
            mma16816(c[3], al, fh[2], fh[3]);
        }
        __syncthreads();
    }

    int rl0 = m0 + (lane >> 2);
    int cbase = n0b + nw0 + (lane & 3) * 2;
#pragma unroll
    for (int half = 0; half < 2; half++) {
        int rl = rl0 + half * 8;
        if (r0 + rl < cnt) {
            int   t = toks[rl];
            float w = ws[rl];
            float* dst = out + (size_t)t * HH;
#pragma unroll
            for (int nt = 0; nt < 4; nt++) {
                int col = cbase + nt * 8;
                atomicAdd(dst + col,     w * c[nt][half*2+0]);
                atomicAdd(dst + col + 1, w * c[nt][half*2+1]);
            }
        }
    }
}

// ---------------- launch ----------------
extern "C" void kernel_launch(void* const* d_in, const int* in_sizes, int n_in,
                              void* d_out, int out_size) {
    const float* x    = (const float*)d_in[0];
    const float* cent = (const float*)d_in[1];
    const float* gw   = (const float*)d_in[2];
    const float* uw   = (const float*)d_in[3];
    const float* dw   = (const float*)d_in[4];
    const float* bias = (const float*)d_in[5];
    float* out = (float*)d_out;

    int write_counts = (out_size >= TT * HH + EE) ? 1 : 0;
    int nsplit = 3 * NG4 + NX4;

    k_zero<<<2048, 256>>>(out);
    k_split<<<(nsplit + 255) / 256, 256>>>((const float4*)gw, (const float4*)uw,
                                           (const float4*)dw, (const float4*)x);
    k_router<<<TT / 8, 256>>>(x, cent, bias);
    k_prefix<<<1, 32>>>(out, write_counts);
    k_gateup<<<dim3(DFFC / 64, TT / 64, EE), 256>>>();
    k_down  <<<dim3(HH / 64, TT / 64, EE), 256>>>(out);
}

// round 5
// speedup vs baseline: 2.2520x; 1.2294x over previous
#include <cuda_runtime.h>
#include <cuda_bf16.h>
#include <math.h>
#include <stdint.h>

#define TT   4096
#define EE   8
#define HH   1024
#define DFFC 2048
#define PP   (TT*2)

// ---------------- device scratch ----------------
__device__ int   g_cnt[EE];
__device__ int   g_base[EE];
__device__ int   g_tok[EE][TT];
__device__ float g_wt [EE][TT];

__device__ __nv_bfloat16 g_xh[TT*HH],        g_xl[TT*HH];
__device__ __nv_bfloat16 g_gwh[EE*DFFC*HH],  g_gwl[EE*DFFC*HH];
__device__ __nv_bfloat16 g_uwh[EE*DFFC*HH],  g_uwl[EE*DFFC*HH];
__device__ __nv_bfloat16 g_dwh[EE*HH*DFFC],  g_dwl[EE*HH*DFFC];
__device__ __nv_bfloat16 g_ih[(size_t)PP*DFFC], g_il[(size_t)PP*DFFC];

// ---------------- helpers ----------------
__device__ __forceinline__ __nv_bfloat16 bfhi(float a) { return __float2bfloat16(a); }
__device__ __forceinline__ __nv_bfloat16 bflo(float a, __nv_bfloat16 h) {
    return __float2bfloat16(a - __bfloat162float(h));
}
__device__ __forceinline__ uint32_t s2u(const void* p) {
    return (uint32_t)__cvta_generic_to_shared(p);
}
__device__ __forceinline__ void cp16(uint32_t dst, const void* src) {
    asm volatile("cp.async.cg.shared.global [%0], [%1], 16;" :: "r"(dst), "l"(src) : "memory");
}
#define CP_COMMIT() asm volatile("cp.async.commit_group;" ::: "memory")
#define CP_WAIT1()  asm volatile("cp.async.wait_group 1;" ::: "memory")
#define CP_WAIT0()  asm volatile("cp.async.wait_group 0;" ::: "memory")

__device__ __forceinline__ void ldsm4(unsigned &r0, unsigned &r1, unsigned &r2, unsigned &r3,
                                      unsigned addr) {
    asm volatile("ldmatrix.sync.aligned.m8n8.x4.shared.b16 {%0,%1,%2,%3}, [%4];"
                 : "=r"(r0), "=r"(r1), "=r"(r2), "=r"(r3) : "r"(addr));
}
__device__ __forceinline__ void mma16816(float c[4], const unsigned a[4],
                                         unsigned b0, unsigned b1) {
    asm volatile("mma.sync.aligned.m16n8k16.row.col.f32.bf16.bf16.f32 "
                 "{%0,%1,%2,%3}, {%4,%5,%6,%7}, {%8,%9}, {%0,%1,%2,%3};"
                 : "+f"(c[0]), "+f"(c[1]), "+f"(c[2]), "+f"(c[3])
                 : "r"(a[0]), "r"(a[1]), "r"(a[2]), "r"(a[3]), "r"(b0), "r"(b1));
}
// 16x16 A fragment at (m0, k=ks*16), smem tile row stride 80B
__device__ __forceinline__ void ldfragA(unsigned f[4], unsigned base, int m0, int ks, int lane) {
    int sub = lane >> 3;
    int r   = m0 + (lane & 7) + ((sub & 1) << 3);
    int kg  = (ks << 1) + (sub >> 1);
    ldsm4(f[0], f[1], f[2], f[3], base + r * 80 + (kg << 4));
}
// B fragments for 2 adjacent n8 tiles (n0..n0+15) at k=ks*16
__device__ __forceinline__ void ldfragB(unsigned f[4], unsigned base, int n0, int ks, int lane) {
    int sub = lane >> 3;
    int r   = n0 + (lane & 7) + ((sub >> 1) << 3);
    int kg  = (ks << 1) + (sub & 1);
    ldsm4(f[0], f[1], f[2], f[3], base + r * 80 + (kg << 4));
}
// c += AH*BH + AH*BL + AL*BH   (3-term split product)
#define MMA3(cc, AH, AL, BH0, BH1, BL0, BL1) do { \
    mma16816(cc, AH, BH0, BH1); \
    mma16816(cc, AH, BL0, BL1); \
    mma16816(cc, AL, BH0, BH1); } while (0)

__device__ __forceinline__ void red2(float* p, float x, float y) {
    asm volatile("red.global.add.v2.f32 [%0], {%1,%2};" :: "l"(p), "f"(x), "f"(y) : "memory");
}

// ---------------- kernel: zero out + counters ----------------
__global__ void k_zero(float* out) {
    int i = blockIdx.x * blockDim.x + threadIdx.x;
    if (i < EE) g_cnt[i] = 0;
    for (size_t j = i; j < (size_t)TT * HH; j += (size_t)gridDim.x * blockDim.x)
        out[j] = 0.f;
}

// ---------------- kernel: split fp32 -> bf16 hi/lo ----------------
#define NG4 (EE*DFFC*HH/4)
#define NX4 (TT*HH/4)
__global__ void k_split(const float4* __restrict__ gw, const float4* __restrict__ uw,
                        const float4* __restrict__ dw, const float4* __restrict__ x) {
    int i = blockIdx.x * blockDim.x + threadIdx.x;
    const float4* src; __nv_bfloat16* hi; __nv_bfloat16* lo; int idx;
    if      (i < NG4)          { src = gw; hi = g_gwh; lo = g_gwl; idx = i; }
    else if (i < 2*NG4)        { src = uw; hi = g_uwh; lo = g_uwl; idx = i - NG4; }
    else if (i < 3*NG4)        { src = dw; hi = g_dwh; lo = g_dwl; idx = i - 2*NG4; }
    else if (i < 3*NG4 + NX4)  { src = x;  hi = g_xh;  lo = g_xl;  idx = i - 3*NG4; }
    else return;
    float4 v = src[idx];
    __nv_bfloat162 h0, h1, l0, l1;
    h0.x = bfhi(v.x); l0.x = bflo(v.x, h0.x);
    h0.y = bfhi(v.y); l0.y = bflo(v.y, h0.y);
    h1.x = bfhi(v.z); l1.x = bflo(v.z, h1.x);
    h1.y = bfhi(v.w); l1.y = bflo(v.w, h1.y);
    ((__nv_bfloat162*)hi)[2*idx] = h0; ((__nv_bfloat162*)hi)[2*idx+1] = h1;
    ((__nv_bfloat162*)lo)[2*idx] = l0; ((__nv_bfloat162*)lo)[2*idx+1] = l1;
}

// ---------------- kernel: router ----------------
__global__ void k_router(const float* __restrict__ x, const float* __restrict__ cent,
                         const float* __restrict__ bias) {
    int warp = threadIdx.x >> 5, lane = threadIdx.x & 31;
    int t = blockIdx.x * 8 + warp;
    if (t >= TT) return;
    const float* xr = x + (size_t)t * HH;
    float acc[EE];
#pragma unroll
    for (int e = 0; e < EE; e++) acc[e] = 0.f;
    for (int h = lane; h < HH; h += 32) {
        float xv = xr[h];
#pragma unroll
        for (int e = 0; e < EE; e++) acc[e] += xv * cent[e * HH + h];
    }
#pragma unroll
    for (int e = 0; e < EE; e++)
#pragma unroll
        for (int o = 16; o > 0; o >>= 1)
            acc[e] += __shfl_down_sync(0xffffffffu, acc[e], o);
    if (lane == 0) {
        float s[EE];
#pragma unroll
        for (int e = 0; e < EE; e++)
            s[e] = 1.f / (1.f + expf(-acc[e])) + bias[e];
        float v0 = -1e30f; int i0 = 0;
#pragma unroll
        for (int e = 0; e < EE; e++) if (s[e] > v0) { v0 = s[e]; i0 = e; }
        float v1 = -1e30f; int i1 = 0;
#pragma unroll
        for (int e = 0; e < EE; e++) if (e != i0 && s[e] > v1) { v1 = s[e]; i1 = e; }
        float e1 = expf(v1 - v0);
        float w0 = 1.f / (1.f + e1), w1 = e1 * w0;
        int s0 = atomicAdd(&g_cnt[i0], 1);
        g_tok[i0][s0] = t; g_wt[i0][s0] = w0;
        int s1 = atomicAdd(&g_cnt[i1], 1);
        g_tok[i1][s1] = t; g_wt[i1][s1] = w1;
    }
}

__global__ void k_prefix(float* out, int write_counts) {
    if (threadIdx.x == 0) {
        int b = 0;
        for (int e = 0; e < EE; e++) { g_base[e] = b; b += g_cnt[e]; }
    }
    __syncthreads();
    if (write_counts && threadIdx.x < EE)
        out[(size_t)TT * HH + threadIdx.x] = (float)g_cnt[threadIdx.x];
}

// ============ gate/up grouped GEMM + fused SwiGLU (mma.sync, cp.async x3) ====
// CTA: 64 tokens x 64 dff (both gate & up), BK=32, 128 thr.
// Warp (2x2): m32 x n32 per matrix. 3-stage cp.async pipeline.
#define GU_TILE  5120                 // 64 rows * 80B
#define GU_STAGE (6*GU_TILE)          // Ah Al Gh Gl Uh Ul
#define GU_NS    3
__global__ __launch_bounds__(128) void k_gateup_mma() {
    int e   = blockIdx.z;
    int cnt = g_cnt[e];
    int r0  = blockIdx.y * 64;
    if (r0 >= cnt) return;
    int n0  = blockIdx.x * 64;

    extern __shared__ __align__(128) char smx[];
    __shared__ int toks[64];

    int tid = threadIdx.x, lane = tid & 31, warp = tid >> 5;
    if (tid < 64) toks[tid] = (r0 + tid < cnt) ? g_tok[e][r0 + tid] : g_tok[e][0];
    __syncthreads();

    uint32_t sbase = s2u(smx);
    int row0 = tid >> 2, kg = tid & 3;

    const char* pxh = (const char*)g_xh;  const char* pxl = (const char*)g_xl;
    const char* pgh = (const char*)g_gwh; const char* pgl = (const char*)g_gwl;
    const char* puh = (const char*)g_uwh; const char* pul = (const char*)g_uwl;

    uint32_t a0 = (uint32_t)toks[row0]      * (HH*2) + kg*16;
    uint32_t a1 = (uint32_t)toks[row0 + 32] * (HH*2) + kg*16;
    uint32_t wofs = (uint32_t)(e * DFFC + n0) * (HH*2);
    uint32_t w0 = wofs + (uint32_t)row0        * (HH*2) + kg*16;
    uint32_t w1 = wofs + (uint32_t)(row0 + 32) * (HH*2) + kg*16;
    uint32_t so0 = row0 * 80 + kg * 16, so1 = so0 + 2560;

    auto issue = [&](int kt) {
        uint32_t sb = sbase + (kt % GU_NS) * GU_STAGE;
        uint32_t kb = (uint32_t)kt * 64;
        cp16(sb             + so0, pxh + a0 + kb); cp16(sb             + so1, pxh + a1 + kb);
        cp16(sb +   GU_TILE + so0, pxl + a0 + kb); cp16(sb +   GU_TILE + so1, pxl + a1 + kb);
        cp16(sb + 2*GU_TILE + so0, pgh + w0 + kb); cp16(sb + 2*GU_TILE + so1, pgh + w1 + kb);
        cp16(sb + 3*GU_TILE + so0, pgl + w0 + kb); cp16(sb + 3*GU_TILE + so1, pgl + w1 + kb);
        cp16(sb + 4*GU_TILE + so0, puh + w0 + kb); cp16(sb + 4*GU_TILE + so1, puh + w1 + kb);
        cp16(sb + 5*GU_TILE + so0, pul + w0 + kb); cp16(sb + 5*GU_TILE + so1, pul + w1 + kb);
        CP_COMMIT();
    };

    issue(0); issue(1);

    int wm = warp >> 1, wn = warp & 1;
    int m0 = wm * 32, nb = wn * 32;

    float cg[2][4][4], cu[2][4][4];
#pragma unroll
    for (int a = 0; a < 2; a++)
#pragma unroll
        for (int b = 0; b < 4; b++)
#pragma unroll
            for (int c = 0; c < 4; c++) { cg[a][b][c] = 0.f; cu[a][b][c] = 0.f; }

    const int NT = HH / 32;
    for (int kt = 0; kt < NT; kt++) {
        // TAIL FIX: last stage has no group committed after it; wait_group 1
        // would let the stage we are about to read stay in flight.
        if (kt < NT - 1) CP_WAIT1(); else CP_WAIT0();
        __syncthreads();
        if (kt + 2 < NT) issue(kt + 2);

        uint32_t sb  = sbase + (kt % GU_NS) * GU_STAGE;
        uint32_t sAh = sb, sAl = sb + GU_TILE;
        uint32_t sGh = sb + 2*GU_TILE, sGl = sb + 3*GU_TILE;
        uint32_t sUh = sb + 4*GU_TILE, sUl = sb + 5*GU_TILE;

#pragma unroll
        for (int ks = 0; ks < 2; ks++) {
            unsigned ah0[4], ah1[4], al0[4], al1[4], fh[4], fl[4];
            ldfragA(ah0, sAh, m0,      ks, lane);
            ldfragA(ah1, sAh, m0 + 16, ks, lane);
            ldfragA(al0, sAl, m0,      ks, lane);
            ldfragA(al1, sAl, m0 + 16, ks, lane);
#pragma unroll
            for (int ng = 0; ng < 2; ng++) {
                ldfragB(fh, sGh, nb + ng*16, ks, lane);
                ldfragB(fl, sGl, nb + ng*16, ks, lane);
                MMA3(cg[0][2*ng],   ah0, al0, fh[0], fh[1], fl[0], fl[1]);
                MMA3(cg[0][2*ng+1], ah0, al0, fh[2], fh[3], fl[2], fl[3]);
                MMA3(cg[1][2*ng],   ah1, al1, fh[0], fh[1], fl[0], fl[1]);
                MMA3(cg[1][2*ng+1], ah1, al1, fh[2], fh[3], fl[2], fl[3]);
            }
#pragma unroll
            for (int ng = 0; ng < 2; ng++) {
                ldfragB(fh, sUh, nb + ng*16, ks, lane);
                ldfragB(fl, sUl, nb + ng*16, ks, lane);
                MMA3(cu[0][2*ng],   ah0, al0, fh[0], fh[1], fl[0], fl[1]);
                MMA3(cu[0][2*ng+1], ah0, al0, fh[2], fh[3], fl[2], fl[3]);
                MMA3(cu[1][2*ng],   ah1, al1, fh[0], fh[1], fl[0], fl[1]);
                MMA3(cu[1][2*ng+1], ah1, al1, fh[2], fh[3], fl[2], fl[3]);
            }
        }
    }

    // epilogue: SwiGLU in registers, split to bf16 hi/lo, store intermediate
    int pb = g_base[e] + r0;
#pragma unroll
    for (int mi = 0; mi < 2; mi++)
#pragma unroll
        for (int half = 0; half < 2; half++) {
            int rl = m0 + mi*16 + (lane >> 2) + half*8;
            if (r0 + rl < cnt) {
                size_t p = (size_t)(pb + rl);
#pragma unroll
                for (int j = 0; j < 4; j++) {
                    int col = n0 + nb + j*8 + (lane & 3)*2;
                    float g0 = cg[mi][j][half*2+0], g1 = cg[mi][j][half*2+1];
                    float u0 = cu[mi][j][half*2+0], u1 = cu[mi][j][half*2+1];
                    float h0 = (g0 / (1.f + expf(-g0))) * u0;
                    float h1 = (g1 / (1.f + expf(-g1))) * u1;
                    __nv_bfloat162 vh, vl;
                    vh.x = bfhi(h0); vl.x = bflo(h0, vh.x);
                    vh.y = bfhi(h1); vl.y = bflo(h1, vh.y);
                    *(__nv_bfloat162*)(g_ih + p * DFFC + col) = vh;
                    *(__nv_bfloat162*)(g_il + p * DFFC + col) = vl;
                }
            }
        }
}

// ============ down grouped GEMM + weighted scatter (mma.sync, cp.async x3) ===
// CTA: 64 pairs x 128 H, BK=32, 128 thr. Warp (2x2): m32 x n64.
#define DN_ATILE 5120                 // 64 * 80
#define DN_BTILE 10240                // 128 * 80
#define DN_STAGE (2*DN_ATILE + 2*DN_BTILE)   // 30720
#define DN_NS    3
__global__ __launch_bounds__(128) void k_down_mma(float* __restrict__ out) {
    int e   = blockIdx.z;
    int cnt = g_cnt[e];
    int r0  = blockIdx.y * 64;
    if (r0 >= cnt) return;
    int n0  = blockIdx.x * 128;

    extern __shared__ __align__(128) char smx[];
    __shared__ int   toks[64];
    __shared__ float ws[64];
    __shared__ int   prows[64];

    int tid = threadIdx.x, lane = tid & 31, warp = tid >> 5;
    if (tid < 64) {
        bool ok = (r0 + tid) < cnt;
        toks[tid]  = ok ? g_tok[e][r0 + tid] : 0;
        ws[tid]    = ok ? g_wt [e][r0 + tid] : 0.f;
        prows[tid] = ok ? (g_base[e] + r0 + tid) : g_base[e];
    }
    __syncthreads();

    uint32_t sbase = s2u(smx);
    int row0 = tid >> 2, kg = tid & 3;

    const char* pih = (const char*)g_ih;  const char* pil = (const char*)g_il;
    const char* pdh = (const char*)g_dwh; const char* pdl = (const char*)g_dwl;

    uint32_t a0 = (uint32_t)prows[row0]      * (DFFC*2) + kg*16;
    uint32_t a1 = (uint32_t)prows[row0 + 32] * (DFFC*2) + kg*16;
    uint32_t wofs = (uint32_t)(e * HH + n0) * (DFFC*2);
    uint32_t b0 = wofs + (uint32_t)row0        * (DFFC*2) + kg*16;
    uint32_t b1 = wofs + (uint32_t)(row0 + 32) * (DFFC*2) + kg*16;
    uint32_t b2 = wofs + (uint32_t)(row0 + 64) * (DFFC*2) + kg*16;
    uint32_t b3 = wofs + (uint32_t)(row0 + 96) * (DFFC*2) + kg*16;
    uint32_t so0 = row0 * 80 + kg * 16;

    auto issue = [&](int kt) {
        uint32_t sb = sbase + (kt % DN_NS) * DN_STAGE;
        uint32_t kb = (uint32_t)kt * 64;
        uint32_t sA = sb, sL = sb + DN_ATILE;
        uint32_t sBh = sb + 2*DN_ATILE, sBl = sBh + DN_BTILE;
        cp16(sA + so0,        pih + a0 + kb); cp16(sA + so0 + 2560, pih + a1 + kb);
        cp16(sL + so0,        pil + a0 + kb); cp16(sL + so0 + 2560, pil + a1 + kb);
        cp16(sBh + so0,        pdh + b0 + kb); cp16(sBh + so0 + 2560, pdh + b1 + kb);
        cp16(sBh + so0 + 5120, pdh + b2 + kb); cp16(sBh + so0 + 7680, pdh + b3 + kb);
        cp16(sBl + so0,        pdl + b0 + kb); cp16(sBl + so0 + 2560, pdl + b1 + kb);
        cp16(sBl + so0 + 5120, pdl + b2 + kb); cp16(sBl + so0 + 7680, pdl + b3 + kb);
        CP_COMMIT();
    };

    issue(0); issue(1);

    int wm = warp >> 1, wn = warp & 1;
    int m0 = wm * 32, nb = wn * 64;

    float c[2][8][4];
#pragma unroll
    for (int a = 0; a < 2; a++)
#pragma unroll
        for (int b = 0; b < 8; b++)
#pragma unroll
            for (int k = 0; k < 4; k++) c[a][b][k] = 0.f;

    const int NT = DFFC / 32;
    for (int kt = 0; kt < NT; kt++) {
        // TAIL FIX (same as gate/up): final stage must be fully drained.
        if (kt < NT - 1) CP_WAIT1(); else CP_WAIT0();
        __syncthreads();
        if (kt + 2 < NT) issue(kt + 2);

        uint32_t sb  = sbase + (kt % DN_NS) * DN_STAGE;
        uint32_t sAh = sb, sAl = sb + DN_ATILE;
        uint32_t sBh = sb + 2*DN_ATILE, sBl = sBh + DN_BTILE;

#pragma unroll
        for (int ks = 0; ks < 2; ks++) {
            unsigned ah0[4], ah1[4], al0[4], al1[4], fh[4], fl[4];
            ldfragA(ah0, sAh, m0,      ks, lane);
            ldfragA(ah1, sAh, m0 + 16, ks, lane);
            ldfragA(al0, sAl, m0,      ks, lane);
            ldfragA(al1, sAl, m0 + 16, ks, lane);
#pragma unroll
            for (int ng = 0; ng < 4; ng++) {
                ldfragB(fh, sBh, nb + ng*16, ks, lane);
                ldfragB(fl, sBl, nb + ng*16, ks, lane);
                MMA3(c[0][2*ng],   ah0, al0, fh[0], fh[1], fl[0], fl[1]);
                MMA3(c[0][2*ng+1], ah0, al0, fh[2], fh[3], fl[2], fl[3]);
                MMA3(c[1][2*ng],   ah1, al1, fh[0], fh[1], fl[0], fl[1]);
                MMA3(c[1][2*ng+1], ah1, al1, fh[2], fh[3], fl[2], fl[3]);
            }
        }
    }

    // epilogue: weighted vector-atomic scatter
#pragma unroll
    for (int mi = 0; mi < 2; mi++)
#pragma unroll
        for (int half = 0; half < 2; half++) {
            int rl = m0 + mi*16 + (lane >> 2) + half*8;
            if (r0 + rl < cnt) {
                int   t = toks[rl];
                float w = ws[rl];
                float* dst = out + (size_t)t * HH;
#pragma unroll
                for (int j = 0; j < 8; j++) {
                    int col = n0 + nb + j*8 + (lane & 3)*2;
                    red2(dst + col, w * c[mi][j][half*2+0], w * c[mi][j][half*2+1]);
                }
            }
        }
}

// ---------------- launch ----------------
extern "C" void kernel_launch(void* const* d_in, const int* in_sizes, int n_in,
                              void* d_out, int out_size) {
    const float* x    = (const float*)d_in[0];
    const float* cent = (const float*)d_in[1];
    const float* gw   = (const float*)d_in[2];
    const float* uw   = (const float*)d_in[3];
    const float* dw   = (const float*)d_in[4];
    const float* bias = (const float*)d_in[5];
    float* out = (float*)d_out;

    int write_counts = (out_size >= TT * HH + EE) ? 1 : 0;
    int nsplit = 3 * NG4 + NX4;

    cudaFuncSetAttribute(k_gateup_mma, cudaFuncAttributeMaxDynamicSharedMemorySize,
                         GU_NS * GU_STAGE);
    cudaFuncSetAttribute(k_down_mma, cudaFuncAttributeMaxDynamicSharedMemorySize,
                         DN_NS * DN_STAGE);

    k_zero<<<2048, 256>>>(out);
    k_split<<<(nsplit + 255) / 256, 256>>>((const float4*)gw, (const float4*)uw,
                                           (const float4*)dw, (const float4*)x);
    k_router<<<TT / 8, 256>>>(x, cent, bias);
    k_prefix<<<1, 32>>>(out, write_counts);
    k_gateup_mma<<<dim3(DFFC / 64, TT / 64, EE), 128, GU_NS * GU_STAGE>>>();
    k_down_mma  <<<dim3(HH / 128, TT / 64, EE), 128, DN_NS * DN_STAGE>>>(out);
}

// round 6
// speedup vs baseline: 5.6534x; 2.5103x over previous
#include <cuda_runtime.h>
#include <cuda_fp16.h>
#include <math.h>
#include <stdint.h>

#define TT   4096
#define EE   8
#define HH   1024
#define DFFC 2048
#define PP   (TT*2)

// ---------------- device scratch ----------------
__device__ int   g_cnt[EE];
__device__ int   g_base[EE];
__device__ int   g_tok[EE][TT];
__device__ float g_wt [EE][TT];

__device__ __half g_xq[TT*HH];
__device__ __half g_gq[EE*DFFC*HH];
__device__ __half g_uq[EE*DFFC*HH];
__device__ __half g_dq[EE*HH*DFFC];
__device__ __half g_iq[(size_t)PP*DFFC];

// ---------------- helpers ----------------
__device__ __forceinline__ uint32_t s2u(const void* p) {
    return (uint32_t)__cvta_generic_to_shared(p);
}
__device__ __forceinline__ void cp16(uint32_t dst, const void* src) {
    asm volatile("cp.async.cg.shared.global [%0], [%1], 16;" :: "r"(dst), "l"(src) : "memory");
}
#define CP_COMMIT() asm volatile("cp.async.commit_group;" ::: "memory")
#define CP_WAIT1()  asm volatile("cp.async.wait_group 1;" ::: "memory")
#define CP_WAIT0()  asm volatile("cp.async.wait_group 0;" ::: "memory")

__device__ __forceinline__ void ldsm4(unsigned &r0, unsigned &r1, unsigned &r2, unsigned &r3,
                                      unsigned addr) {
    asm volatile("ldmatrix.sync.aligned.m8n8.x4.shared.b16 {%0,%1,%2,%3}, [%4];"
                 : "=r"(r0), "=r"(r1), "=r"(r2), "=r"(r3) : "r"(addr));
}
__device__ __forceinline__ void mma16816(float c[4], const unsigned a[4],
                                         unsigned b0, unsigned b1) {
    asm volatile("mma.sync.aligned.m16n8k16.row.col.f32.f16.f16.f32 "
                 "{%0,%1,%2,%3}, {%4,%5,%6,%7}, {%8,%9}, {%0,%1,%2,%3};"
                 : "+f"(c[0]), "+f"(c[1]), "+f"(c[2]), "+f"(c[3])
                 : "r"(a[0]), "r"(a[1]), "r"(a[2]), "r"(a[3]), "r"(b0), "r"(b1));
}
// 16x16 A fragment at (m0, k=ks*16), smem tile row stride 80B
__device__ __forceinline__ void ldfragA(unsigned f[4], unsigned base, int m0, int ks, int lane) {
    int sub = lane >> 3;
    int r   = m0 + (lane & 7) + ((sub & 1) << 3);
    int kg  = (ks << 1) + (sub >> 1);
    ldsm4(f[0], f[1], f[2], f[3], base + r * 80 + (kg << 4));
}
// B fragments for 2 adjacent n8 tiles (n0..n0+15) at k=ks*16
__device__ __forceinline__ void ldfragB(unsigned f[4], unsigned base, int n0, int ks, int lane) {
    int sub = lane >> 3;
    int r   = n0 + (lane & 7) + ((sub >> 1) << 3);
    int kg  = (ks << 1) + (sub & 1);
    ldsm4(f[0], f[1], f[2], f[3], base + r * 80 + (kg << 4));
}
__device__ __forceinline__ void red2(float* p, float x, float y) {
    asm volatile("red.global.add.v2.f32 [%0], {%1,%2};" :: "l"(p), "f"(x), "f"(y) : "memory");
}

// ---------------- kernel: zero out + counters ----------------
__global__ void k_zero(float* out) {
    int i = blockIdx.x * blockDim.x + threadIdx.x;
    if (i < EE) g_cnt[i] = 0;
    for (size_t j = i; j < (size_t)TT * HH; j += (size_t)gridDim.x * blockDim.x)
        out[j] = 0.f;
}

// ---------------- kernel: convert fp32 -> fp16 ----------------
#define NG4 (EE*DFFC*HH/4)
#define NX4 (TT*HH/4)
__global__ void k_conv(const float4* __restrict__ gw, const float4* __restrict__ uw,
                       const float4* __restrict__ dw, const float4* __restrict__ x) {
    int i = blockIdx.x * blockDim.x + threadIdx.x;
    const float4* src; __half* dst; int idx;
    if      (i < NG4)          { src = gw; dst = g_gq; idx = i; }
    else if (i < 2*NG4)        { src = uw; dst = g_uq; idx = i - NG4; }
    else if (i < 3*NG4)        { src = dw; dst = g_dq; idx = i - 2*NG4; }
    else if (i < 3*NG4 + NX4)  { src = x;  dst = g_xq; idx = i - 3*NG4; }
    else return;
    float4 v = src[idx];
    __half2 h0 = __floats2half2_rn(v.x, v.y);
    __half2 h1 = __floats2half2_rn(v.z, v.w);
    ((__half2*)dst)[2*idx]   = h0;
    ((__half2*)dst)[2*idx+1] = h1;
}

// ---------------- kernel: router ----------------
__global__ void k_router(const float* __restrict__ x, const float* __restrict__ cent,
                         const float* __restrict__ bias) {
    int warp = threadIdx.x >> 5, lane = threadIdx.x & 31;
    int t = blockIdx.x * 8 + warp;
    if (t >= TT) return;
    const float* xr = x + (size_t)t * HH;
    float acc[EE];
#pragma unroll
    for (int e = 0; e < EE; e++) acc[e] = 0.f;
    for (int h = lane; h < HH; h += 32) {
        float xv = xr[h];
#pragma unroll
        for (int e = 0; e < EE; e++) acc[e] += xv * cent[e * HH + h];
    }
#pragma unroll
    for (int e = 0; e < EE; e++)
#pragma unroll
        for (int o = 16; o > 0; o >>= 1)
            acc[e] += __shfl_down_sync(0xffffffffu, acc[e], o);
    if (lane == 0) {
        float s[EE];
#pragma unroll
        for (int e = 0; e < EE; e++)
            s[e] = 1.f / (1.f + expf(-acc[e])) + bias[e];
        float v0 = -1e30f; int i0 = 0;
#pragma unroll
        for (int e = 0; e < EE; e++) if (s[e] > v0) { v0 = s[e]; i0 = e; }
        float v1 = -1e30f; int i1 = 0;
#pragma unroll
        for (int e = 0; e < EE; e++) if (e != i0 && s[e] > v1) { v1 = s[e]; i1 = e; }
        float e1 = expf(v1 - v0);
        float w0 = 1.f / (1.f + e1), w1 = e1 * w0;
        int s0 = atomicAdd(&g_cnt[i0], 1);
        g_tok[i0][s0] = t; g_wt[i0][s0] = w0;
        int s1 = atomicAdd(&g_cnt[i1], 1);
        g_tok[i1][s1] = t; g_wt[i1][s1] = w1;
    }
}

__global__ void k_prefix(float* out, int write_counts) {
    if (threadIdx.x == 0) {
        int b = 0;
        for (int e = 0; e < EE; e++) { g_base[e] = b; b += g_cnt[e]; }
    }
    __syncthreads();
    if (write_counts && threadIdx.x < EE)
        out[(size_t)TT * HH + threadIdx.x] = (float)g_cnt[threadIdx.x];
}

// ============ gate/up grouped GEMM + fused SwiGLU (fp16 mma, cp.async x3) ====
// CTA: 64 tokens x 64 dff (both gate & up), BK=32, 128 thr.
// Warp (2x2): m32 x n32 per matrix. 3-stage cp.async pipeline.
#define GU_TILE  5120                 // 64 rows * 80B
#define GU_STAGE (3*GU_TILE)          // A G U
#define GU_NS    3
__global__ __launch_bounds__(128) void k_gateup_mma() {
    int e   = blockIdx.z;
    int cnt = g_cnt[e];
    int r0  = blockIdx.y * 64;
    if (r0 >= cnt) return;
    int n0  = blockIdx.x * 64;

    extern __shared__ __align__(128) char smx[];
    __shared__ int toks[64];

    int tid = threadIdx.x, lane = tid & 31, warp = tid >> 5;
    if (tid < 64) toks[tid] = (r0 + tid < cnt) ? g_tok[e][r0 + tid] : g_tok[e][0];
    __syncthreads();

    uint32_t sbase = s2u(smx);
    int row0 = tid >> 2, kg = tid & 3;

    const char* px = (const char*)g_xq;
    const char* pg = (const char*)g_gq;
    const char* pu = (const char*)g_uq;

    uint32_t a0 = (uint32_t)toks[row0]      * (HH*2) + kg*16;
    uint32_t a1 = (uint32_t)toks[row0 + 32] * (HH*2) + kg*16;
    uint32_t wofs = (uint32_t)(e * DFFC + n0) * (HH*2);
    uint32_t w0 = wofs + (uint32_t)row0        * (HH*2) + kg*16;
    uint32_t w1 = wofs + (uint32_t)(row0 + 32) * (HH*2) + kg*16;
    uint32_t so0 = row0 * 80 + kg * 16, so1 = so0 + 2560;

    auto issue = [&](int kt) {
        uint32_t sb = sbase + (kt % GU_NS) * GU_STAGE;
        uint32_t kb = (uint32_t)kt * 64;
        cp16(sb             + so0, px + a0 + kb); cp16(sb             + so1, px + a1 + kb);
        cp16(sb +   GU_TILE + so0, pg + w0 + kb); cp16(sb +   GU_TILE + so1, pg + w1 + kb);
        cp16(sb + 2*GU_TILE + so0, pu + w0 + kb); cp16(sb + 2*GU_TILE + so1, pu + w1 + kb);
        CP_COMMIT();
    };

    issue(0); issue(1);

    int wm = warp >> 1, wn = warp & 1;
    int m0 = wm * 32, nb = wn * 32;

    float cg[2][4][4], cu[2][4][4];
#pragma unroll
    for (int a = 0; a < 2; a++)
#pragma unroll
        for (int b = 0; b < 4; b++)
#pragma unroll
            for (int c = 0; c < 4; c++) { cg[a][b][c] = 0.f; cu[a][b][c] = 0.f; }

    const int NT = HH / 32;
    for (int kt = 0; kt < NT; kt++) {
        if (kt < NT - 1) CP_WAIT1(); else CP_WAIT0();   // tail: drain fully
        __syncthreads();
        if (kt + 2 < NT) issue(kt + 2);

        uint32_t sb = sbase + (kt % GU_NS) * GU_STAGE;
        uint32_t sA = sb, sG = sb + GU_TILE, sU = sb + 2*GU_TILE;

#pragma unroll
        for (int ks = 0; ks < 2; ks++) {
            unsigned ah0[4], ah1[4], fh[4];
            ldfragA(ah0, sA, m0,      ks, lane);
            ldfragA(ah1, sA, m0 + 16, ks, lane);
#pragma unroll
            for (int ng = 0; ng < 2; ng++) {
                ldfragB(fh, sG, nb + ng*16, ks, lane);
                mma16816(cg[0][2*ng],   ah0, fh[0], fh[1]);
                mma16816(cg[0][2*ng+1], ah0, fh[2], fh[3]);
                mma16816(cg[1][2*ng],   ah1, fh[0], fh[1]);
                mma16816(cg[1][2*ng+1], ah1, fh[2], fh[3]);
            }
#pragma unroll
            for (int ng = 0; ng < 2; ng++) {
                ldfragB(fh, sU, nb + ng*16, ks, lane);
                mma16816(cu[0][2*ng],   ah0, fh[0], fh[1]);
                mma16816(cu[0][2*ng+1], ah0, fh[2], fh[3]);
                mma16816(cu[1][2*ng],   ah1, fh[0], fh[1]);
                mma16816(cu[1][2*ng+1], ah1, fh[2], fh[3]);
            }
        }
    }

    // epilogue: SwiGLU in fp32 registers, store fp16 intermediate
    int pb = g_base[e] + r0;
#pragma unroll
    for (int mi = 0; mi < 2; mi++)
#pragma unroll
        for (int half = 0; half < 2; half++) {
            int rl = m0 + mi*16 + (lane >> 2) + half*8;
            if (r0 + rl < cnt) {
                size_t p = (size_t)(pb + rl);
#pragma unroll
                for (int j = 0; j < 4; j++) {
                    int col = n0 + nb + j*8 + (lane & 3)*2;
                    float g0 = cg[mi][j][half*2+0], g1 = cg[mi][j][half*2+1];
                    float u0 = cu[mi][j][half*2+0], u1 = cu[mi][j][half*2+1];
                    float h0 = (g0 / (1.f + expf(-g0))) * u0;
                    float h1 = (g1 / (1.f + expf(-g1))) * u1;
                    *(__half2*)(g_iq + p * DFFC + col) = __floats2half2_rn(h0, h1);
                }
            }
        }
}

// ============ down grouped GEMM + weighted scatter (fp16 mma, cp.async x3) ===
// CTA: 64 pairs x 128 H, BK=32, 128 thr. Warp (2x2): m32 x n64.
#define DN_ATILE 5120                 // 64 * 80
#define DN_BTILE 10240                // 128 * 80
#define DN_STAGE (DN_ATILE + DN_BTILE)   // 15360
#define DN_NS    3
__global__ __launch_bounds__(128) void k_down_mma(float* __restrict__ out) {
    int e   = blockIdx.z;
    int cnt = g_cnt[e];
    int r0  = blockIdx.y * 64;
    if (r0 >= cnt) return;
    int n0  = blockIdx.x * 128;

    extern __shared__ __align__(128) char smx[];
    __shared__ int   toks[64];
    __shared__ float ws[64];
    __shared__ int   prows[64];

    int tid = threadIdx.x, lane = tid & 31, warp = tid >> 5;
    if (tid < 64) {
        bool ok = (r0 + tid) < cnt;
        toks[tid]  = ok ? g_tok[e][r0 + tid] : 0;
        ws[tid]    = ok ? g_wt [e][r0 + tid] : 0.f;
        prows[tid] = ok ? (g_base[e] + r0 + tid) : g_base[e];
    }
    __syncthreads();

    uint32_t sbase = s2u(smx);
    int row0 = tid >> 2, kg = tid & 3;

    const char* pi = (const char*)g_iq;
    const char* pd = (const char*)g_dq;

    uint32_t a0 = (uint32_t)prows[row0]      * (DFFC*2) + kg*16;
    uint32_t a1 = (uint32_t)prows[row0 + 32] * (DFFC*2) + kg*16;
    uint32_t wofs = (uint32_t)(e * HH + n0) * (DFFC*2);
    uint32_t b0 = wofs + (uint32_t)row0        * (DFFC*2) + kg*16;
    uint32_t b1 = wofs + (uint32_t)(row0 + 32) * (DFFC*2) + kg*16;
    uint32_t b2 = wofs + (uint32_t)(row0 + 64) * (DFFC*2) + kg*16;
    uint32_t b3 = wofs + (uint32_t)(row0 + 96) * (DFFC*2) + kg*16;
    uint32_t so0 = row0 * 80 + kg * 16;

    auto issue = [&](int kt) {
        uint32_t sb = sbase + (kt % DN_NS) * DN_STAGE;
        uint32_t kb = (uint32_t)kt * 64;
        uint32_t sA = sb, sB = sb + DN_ATILE;
        cp16(sA + so0,        pi + a0 + kb); cp16(sA + so0 + 2560, pi + a1 + kb);
        cp16(sB + so0,        pd + b0 + kb); cp16(sB + so0 + 2560, pd + b1 + kb);
        cp16(sB + so0 + 5120, pd + b2 + kb); cp16(sB + so0 + 7680, pd + b3 + kb);
        CP_COMMIT();
    };

    issue(0); issue(1);

    int wm = warp >> 1, wn = warp & 1;
    int m0 = wm * 32, nb = wn * 64;

    float c[2][8][4];
#pragma unroll
    for (int a = 0; a < 2; a++)
#pragma unroll
        for (int b = 0; b < 8; b++)
#pragma unroll
            for (int k = 0; k < 4; k++) c[a][b][k] = 0.f;

    const int NT = DFFC / 32;
    for (int kt = 0; kt < NT; kt++) {
        if (kt < NT - 1) CP_WAIT1(); else CP_WAIT0();   // tail: drain fully
        __syncthreads();
        if (kt + 2 < NT) issue(kt + 2);

        uint32_t sb = sbase + (kt % DN_NS) * DN_STAGE;
        uint32_t sA = sb, sB = sb + DN_ATILE;

#pragma unroll
        for (int ks = 0; ks < 2; ks++) {
            unsigned ah0[4], ah1[4], fh[4];
            ldfragA(ah0, sA, m0,      ks, lane);
            ldfragA(ah1, sA, m0 + 16, ks, lane);
#pragma unroll
            for (int ng = 0; ng < 4; ng++) {
                ldfragB(fh, sB, nb + ng*16, ks, lane);
                mma16816(c[0][2*ng],   ah0, fh[0], fh[1]);
                mma16816(c[0][2*ng+1], ah0, fh[2], fh[3]);
                mma16816(c[1][2*ng],   ah1, fh[0], fh[1]);
                mma16816(c[1][2*ng+1], ah1, fh[2], fh[3]);
            }
        }
    }

    // epilogue: weighted vector-atomic scatter
#pragma unroll
    for (int mi = 0; mi < 2; mi++)
#pragma unroll
        for (int half = 0; half < 2; half++) {
            int rl = m0 + mi*16 + (lane >> 2) + half*8;
            if (r0 + rl < cnt) {
                int   t = toks[rl];
                float w = ws[rl];
                float* dst = out + (size_t)t * HH;
#pragma unroll
                for (int j = 0; j < 8; j++) {
                    int col = n0 + nb + j*8 + (lane & 3)*2;
                    red2(dst + col, w * c[mi][j][half*2+0], w * c[mi][j][half*2+1]);
                }
            }
        }
}

// ---------------- launch ----------------
extern "C" void kernel_launch(void* const* d_in, const int* in_sizes, int n_in,
                              void* d_out, int out_size) {
    const float* x    = (const float*)d_in[0];
    const float* cent = (const float*)d_in[1];
    const float* gw   = (const float*)d_in[2];
    const float* uw   = (const float*)d_in[3];
    const float* dw   = (const float*)d_in[4];
    const float* bias = (const float*)d_in[5];
    float* out = (float*)d_out;

    int write_counts = (out_size >= TT * HH + EE) ? 1 : 0;
    int nconv = 3 * NG4 + NX4;

    cudaFuncSetAttribute(k_gateup_mma, cudaFuncAttributeMaxDynamicSharedMemorySize,
                         GU_NS * GU_STAGE);
    cudaFuncSetAttribute(k_down_mma, cudaFuncAttributeMaxDynamicSharedMemorySize,
                         DN_NS * DN_STAGE);

    k_zero<<<2048, 256>>>(out);
    k_conv<<<(nconv + 255) / 256, 256>>>((const float4*)gw, (const float4*)uw,
                                         (const float4*)dw, (const float4*)x);
    k_router<<<TT / 8, 256>>>(x, cent, bias);
    k_prefix<<<1, 32>>>(out, write_counts);
    k_gateup_mma<<<dim3(DFFC / 64, TT / 64, EE), 128, GU_NS * GU_STAGE>>>();
    k_down_mma  <<<dim3(HH / 128, TT / 64, EE), 128, DN_NS * DN_STAGE>>>(out);
}